// round 2
// baseline (speedup 1.0000x reference)
#include <cuda_runtime.h>

// ============================================================================
// RelationalPolicyHead: probs = softmax( relu([emb[s],emb[t]] @ W1 + b1) @ W2 + b2 )
//
// Factorization: W1 = [W1a; W1b] (rows 0..127 / 128..255).
//   A[n] = emb[n] @ W1a + b1   (fold b1 here)
//   B[n] = emb[n] @ W1b
//   logit[e] = sum_j relu(A[s_e][j] + B[t_e][j]) * W2[j] + b2
// Precompute A,B once per node (6.55 GFLOP) instead of per edge (65.5 GFLOP).
// AB table = 102.4 MB fp32 -> L2 resident on GB300 (126 MB L2).
// ============================================================================

#define HID 128
#define NMAX 100000
#define EMAX 1000000

// Scratch (static device globals — no allocations allowed)
__device__ float d_AB[(size_t)NMAX * 256];      // per node: [A(128) | B(128)]
__device__ float d_logits[EMAX];
__device__ int   d_idx[2 * EMAX];               // normalized int32 indices
__device__ float d_partial[2048];               // block partials (max, then sum)
__device__ float d_scalars[2];                  // [0]=gmax, [1]=inv_sum
__device__ unsigned d_flag;                     // index dtype detection

// ---------------------------------------------------------------------------
// 0) reset detection flag
__global__ void k_init() { d_flag = 0u; }

// 1) detect index dtype. ONLY reads the first nwords 32-bit words (= 2E),
//    which exist under both int32 (2E words total) and int64 (4E words total)
//    layouts. If int64: odd words are hi-halves of the first E entries -> all 0.
//    If int32: odd words are real indices -> some nonzero (P[all zero] ~ 0).
__global__ void k_detect(const unsigned* __restrict__ lm32, int nwords) {
    unsigned acc = 0;
    int stride = gridDim.x * blockDim.x;
    int npairs = nwords >> 1;
    for (int i = blockIdx.x * blockDim.x + threadIdx.x; i < npairs; i += stride)
        acc |= lm32[2 * i + 1];
    #pragma unroll
    for (int o = 16; o; o >>= 1) acc |= __shfl_xor_sync(0xffffffffu, acc, o);
    if ((threadIdx.x & 31) == 0 && acc) atomicOr(&d_flag, acc);
}

// 2) normalize indices to int32 in d_idx. Only if detected int64 do we read
//    words beyond 2E (legal then, since the buffer really is 4E words).
__global__ void k_convert(const unsigned* __restrict__ lm32, int total) {
    bool is64 = (d_flag == 0u);
    int stride = gridDim.x * blockDim.x;
    for (int i = blockIdx.x * blockDim.x + threadIdx.x; i < total; i += stride)
        d_idx[i] = (int)(is64 ? lm32[2 * i] : lm32[i]);
}

// ---------------------------------------------------------------------------
// 3) precompute AB = emb @ [W1a | W1b] (+b1 on A half)
//    Persistent grid (148 blocks). W1 staged once per block into smem,
//    rearranged so Wsm[k][j] is the weight for output col j at input dim k.
//    Tile: 16 rows x 256 cols per block-iteration; thread = 4 rows x 4 cols.
#define TROWS 16
__global__ __launch_bounds__(256, 1)
void k_precompute(const float* __restrict__ emb,
                  const float* __restrict__ W1,
                  const float* __restrict__ b1,
                  int nNodes) {
    extern __shared__ float smem[];
    float* Wsm = smem;             // [128][256]  (131072 B)
    float* Esm = smem + 128 * 256; // [16][128]   (8192 B)

    const int tid = threadIdx.x;

    // Stage W1 rearranged: Wsm[k*256 + j]:
    //   j <  128 : W1[k*128 + j]             (A half)
    //   j >= 128 : W1[(128+k)*128 + (j-128)] (B half)
    for (int idx = tid; idx < 128 * 256; idx += 256) {
        int k = idx >> 8, j = idx & 255;
        float v = (j < 128) ? __ldg(&W1[k * 128 + j])
                            : __ldg(&W1[(128 + k) * 128 + (j - 128)]);
        Wsm[idx] = v;
    }

    const int cq = tid & 63;          // col quad: cols cq*4 .. cq*4+3
    const int r4 = (tid >> 6) * 4;    // row base within tile (0,4,8,12)
    // b1 add for this thread's 4 cols (A half only); zeros for B half
    float4 badd = make_float4(0.f, 0.f, 0.f, 0.f);
    if (cq * 4 < 128) badd = __ldg((const float4*)b1 + cq);

    const float4* W4 = (const float4*)Wsm;   // row length 64 float4
    const float4* E4 = (const float4*)Esm;   // row length 32 float4

    int nTiles = (nNodes + TROWS - 1) / TROWS;
    for (int tile = blockIdx.x; tile < nTiles; tile += gridDim.x) {
        int row0 = tile * TROWS;
        __syncthreads();   // protect Esm reuse from previous iteration
        // stage 16 rows of emb (row-major, coalesced float4 copies)
        for (int idx = tid; idx < TROWS * 32; idx += 256) {
            int r = idx >> 5, kq = idx & 31;
            int row = row0 + r;
            float4 v = (row < nNodes)
                ? __ldg((const float4*)emb + (size_t)row * 32 + kq)
                : make_float4(0.f, 0.f, 0.f, 0.f);
            ((float4*)Esm)[r * 32 + kq] = v;
        }
        __syncthreads();

        float acc[4][4];
        #pragma unroll
        for (int r = 0; r < 4; r++)
            #pragma unroll
            for (int j = 0; j < 4; j++) acc[r][j] = 0.f;

        #pragma unroll 4
        for (int k = 0; k < 128; k += 4) {
            float er[4][4];
            #pragma unroll
            for (int r = 0; r < 4; r++) {
                float4 t = E4[(r4 + r) * 32 + (k >> 2)];
                er[r][0] = t.x; er[r][1] = t.y; er[r][2] = t.z; er[r][3] = t.w;
            }
            #pragma unroll
            for (int kk = 0; kk < 4; kk++) {
                float4 wv = W4[(k + kk) * 64 + cq];
                #pragma unroll
                for (int r = 0; r < 4; r++) {
                    float e = er[r][kk];
                    acc[r][0] = fmaf(e, wv.x, acc[r][0]);
                    acc[r][1] = fmaf(e, wv.y, acc[r][1]);
                    acc[r][2] = fmaf(e, wv.z, acc[r][2]);
                    acc[r][3] = fmaf(e, wv.w, acc[r][3]);
                }
            }
        }

        #pragma unroll
        for (int r = 0; r < 4; r++) {
            int row = row0 + r4 + r;
            if (row < nNodes) {
                float4 o = make_float4(acc[r][0] + badd.x, acc[r][1] + badd.y,
                                       acc[r][2] + badd.z, acc[r][3] + badd.w);
                *((float4*)(d_AB + (size_t)row * 256) + cq) = o;
            }
        }
    }
}

// ---------------------------------------------------------------------------
// 4) edge kernel: warp per edge (2 edges in flight),
//    logit[e] = sum relu(A[s]+B[t]) * W2 + b2; block max -> d_partial
__global__ __launch_bounds__(256)
void k_edges(const float* __restrict__ W2, const float* __restrict__ b2, int E) {
    const int lane = threadIdx.x & 31;
    const int wl   = threadIdx.x >> 5;
    const int gw = (blockIdx.x * blockDim.x + threadIdx.x) >> 5;
    const int nw = (gridDim.x * blockDim.x) >> 5;

    float4 w2 = __ldg((const float4*)W2 + lane);
    float bb2 = __ldg(b2);
    float lmax = -3.402823466e38f;

    const int* src = d_idx;
    const int* tgt = d_idx + E;

    for (int e0 = gw; e0 < E; e0 += 2 * nw) {
        int e1 = e0 + nw;
        bool has1 = (e1 < E);
        int s0 = src[e0], t0 = tgt[e0];
        int s1 = has1 ? src[e1] : s0;
        int t1 = has1 ? tgt[e1] : t0;

        float4 a0 = __ldg((const float4*)(d_AB + (size_t)s0 * 256) + lane);
        float4 c0 = __ldg((const float4*)(d_AB + (size_t)t0 * 256 + 128) + lane);
        float4 a1 = __ldg((const float4*)(d_AB + (size_t)s1 * 256) + lane);
        float4 c1 = __ldg((const float4*)(d_AB + (size_t)t1 * 256 + 128) + lane);

        float acc0 = fmaxf(a0.x + c0.x, 0.f) * w2.x + fmaxf(a0.y + c0.y, 0.f) * w2.y
                   + fmaxf(a0.z + c0.z, 0.f) * w2.z + fmaxf(a0.w + c0.w, 0.f) * w2.w;
        float acc1 = fmaxf(a1.x + c1.x, 0.f) * w2.x + fmaxf(a1.y + c1.y, 0.f) * w2.y
                   + fmaxf(a1.z + c1.z, 0.f) * w2.z + fmaxf(a1.w + c1.w, 0.f) * w2.w;

        #pragma unroll
        for (int o = 16; o; o >>= 1) {
            acc0 += __shfl_xor_sync(0xffffffffu, acc0, o);
            acc1 += __shfl_xor_sync(0xffffffffu, acc1, o);
        }
        if (lane == 0) {
            float lg0 = acc0 + bb2;
            d_logits[e0] = lg0;
            lmax = fmaxf(lmax, lg0);
            if (has1) {
                float lg1 = acc1 + bb2;
                d_logits[e1] = lg1;
                lmax = fmaxf(lmax, lg1);
            }
        }
    }

    // block-reduce max
    __shared__ float sm[8];
    #pragma unroll
    for (int o = 16; o; o >>= 1) lmax = fmaxf(lmax, __shfl_xor_sync(0xffffffffu, lmax, o));
    if (lane == 0) sm[wl] = lmax;
    __syncthreads();
    if (threadIdx.x == 0) {
        float m = sm[0];
        #pragma unroll
        for (int i = 1; i < 8; i++) m = fmaxf(m, sm[i]);
        d_partial[blockIdx.x] = m;
    }
}

// 5) reduce block maxima -> gmax (single block, deterministic tree)
__global__ void k_reduce_max(int n) {
    __shared__ float sm[32];
    float m = -3.402823466e38f;
    for (int i = threadIdx.x; i < n; i += blockDim.x) m = fmaxf(m, d_partial[i]);
    #pragma unroll
    for (int o = 16; o; o >>= 1) m = fmaxf(m, __shfl_xor_sync(0xffffffffu, m, o));
    if ((threadIdx.x & 31) == 0) sm[threadIdx.x >> 5] = m;
    __syncthreads();
    if (threadIdx.x < 32) {
        int nwarp = (blockDim.x + 31) >> 5;
        float v = (threadIdx.x < nwarp) ? sm[threadIdx.x] : -3.402823466e38f;
        #pragma unroll
        for (int o = 16; o; o >>= 1) v = fmaxf(v, __shfl_xor_sync(0xffffffffu, v, o));
        if (threadIdx.x == 0) d_scalars[0] = v;
    }
}

// 6) out[e] = exp(logit - gmax); block partial sums -> d_partial
__global__ __launch_bounds__(256)
void k_exp(float* __restrict__ out, int E) {
    float gmax = d_scalars[0];
    float s = 0.f;
    int stride = gridDim.x * blockDim.x;
    for (int i = blockIdx.x * blockDim.x + threadIdx.x; i < E; i += stride) {
        float v = expf(d_logits[i] - gmax);
        out[i] = v;
        s += v;
    }
    __shared__ float sm[8];
    #pragma unroll
    for (int o = 16; o; o >>= 1) s += __shfl_xor_sync(0xffffffffu, s, o);
    if ((threadIdx.x & 31) == 0) sm[threadIdx.x >> 5] = s;
    __syncthreads();
    if (threadIdx.x == 0) {
        float t = 0.f;
        #pragma unroll
        for (int i = 0; i < 8; i++) t += sm[i];
        d_partial[blockIdx.x] = t;
    }
}

// 7) reduce partial sums -> inv_sum
__global__ void k_reduce_sum(int n) {
    __shared__ float sm[32];
    float s = 0.f;
    for (int i = threadIdx.x; i < n; i += blockDim.x) s += d_partial[i];
    #pragma unroll
    for (int o = 16; o; o >>= 1) s += __shfl_xor_sync(0xffffffffu, s, o);
    if ((threadIdx.x & 31) == 0) sm[threadIdx.x >> 5] = s;
    __syncthreads();
    if (threadIdx.x < 32) {
        int nwarp = (blockDim.x + 31) >> 5;
        float v = (threadIdx.x < nwarp) ? sm[threadIdx.x] : 0.f;
        #pragma unroll
        for (int o = 16; o; o >>= 1) v += __shfl_xor_sync(0xffffffffu, v, o);
        if (threadIdx.x == 0) d_scalars[1] = 1.f / v;
    }
}

// 8) normalize in place
__global__ __launch_bounds__(256)
void k_norm(float* __restrict__ out, int E) {
    float inv = d_scalars[1];
    int stride = gridDim.x * blockDim.x;
    for (int i = blockIdx.x * blockDim.x + threadIdx.x; i < E; i += stride)
        out[i] *= inv;
}

// ---------------------------------------------------------------------------
extern "C" void kernel_launch(void* const* d_in, const int* in_sizes, int n_in,
                              void* d_out, int out_size) {
    const float*    emb  = (const float*)d_in[0];
    const unsigned* lm32 = (const unsigned*)d_in[1];   // raw view; dtype detected
    const float*    W1   = (const float*)d_in[2];
    const float*    b1   = (const float*)d_in[3];
    const float*    W2   = (const float*)d_in[4];
    const float*    b2   = (const float*)d_in[5];
    float* out = (float*)d_out;

    int nNodes = in_sizes[0] / HID;
    int E = in_sizes[1] / 2;
    if (nNodes > NMAX) nNodes = NMAX;
    if (E > EMAX) E = EMAX;

    const int SMEM = (128 * 256 + TROWS * 128) * (int)sizeof(float);  // 139264
    cudaFuncSetAttribute(k_precompute, cudaFuncAttributeMaxDynamicSharedMemorySize, SMEM);

    k_init<<<1, 1>>>();
    k_detect<<<256, 256>>>(lm32, 2 * E);   // probes only first 2E words (safe)
    k_convert<<<512, 256>>>(lm32, 2 * E);
    k_precompute<<<148, 256, SMEM>>>(emb, W1, b1, nNodes);
    k_edges<<<592, 256>>>(W2, b2, E);
    k_reduce_max<<<1, 1024>>>(592);
    k_exp<<<1024, 256>>>(out, E);
    k_reduce_sum<<<1, 1024>>>(1024);
    k_norm<<<1024, 256>>>(out, E);
}

// round 3
// speedup vs baseline: 1.0843x; 1.0843x over previous
#include <cuda_runtime.h>

// ============================================================================
// RelationalPolicyHead: probs = softmax( relu([emb[s],emb[t]] @ W1 + b1) @ W2 + b2 )
//
// Factorization: W1 = [W1a; W1b] (rows 0..127 / 128..255).
//   A[n] = emb[n] @ W1a + b1   (fold b1 here)
//   B[n] = emb[n] @ W1b
//   logit[e] = sum_j relu(A[s_e][j] + B[t_e][j]) * W2[j] + b2
// ============================================================================

#define HID 128
#define NMAX 100000
#define EMAX 1000000

__device__ float d_AB[(size_t)NMAX * 256];      // per node: [A(128) | B(128)]
__device__ float d_logits[EMAX];
__device__ int   d_idx[2 * EMAX];               // normalized int32 indices
__device__ float d_partial[2048];               // block partials (max, then sum)
__device__ float d_scalars[2];                  // [0]=gmax, [1]=inv_sum
__device__ unsigned d_flag;                     // index dtype detection

// ---------------------------------------------------------------------------
__global__ void k_init() { d_flag = 0u; }

// detect index dtype: probe ONLY first 2E words (exist in both layouts).
// int64 -> odd words are hi-halves of first E entries -> all zero.
__global__ void k_detect(const unsigned* __restrict__ lm32, int nwords) {
    unsigned acc = 0;
    int stride = gridDim.x * blockDim.x;
    int npairs = nwords >> 1;
    for (int i = blockIdx.x * blockDim.x + threadIdx.x; i < npairs; i += stride)
        acc |= lm32[2 * i + 1];
    #pragma unroll
    for (int o = 16; o; o >>= 1) acc |= __shfl_xor_sync(0xffffffffu, acc, o);
    if ((threadIdx.x & 31) == 0 && acc) atomicOr(&d_flag, acc);
}

__global__ void k_convert(const unsigned* __restrict__ lm32, int total) {
    bool is64 = (d_flag == 0u);
    int stride = gridDim.x * blockDim.x;
    for (int i = blockIdx.x * blockDim.x + threadIdx.x; i < total; i += stride)
        d_idx[i] = (int)(is64 ? lm32[2 * i] : lm32[i]);
}

// ---------------------------------------------------------------------------
// precompute AB = emb @ [W1a | W1b] (+b1 on A half)
// 512 threads (16 warps/SM), 32-row x 256-col tiles, thread = 4x4.
// W staged once per SM into smem (131 KB), Esm 16 KB -> 147 KB, 1 block/SM.
#define TROWS 32
#define PT 512
__global__ __launch_bounds__(PT, 1)
void k_precompute(const float* __restrict__ emb,
                  const float* __restrict__ W1,
                  const float* __restrict__ b1,
                  int nNodes) {
    extern __shared__ float smem[];
    float* Wsm = smem;             // [128][256]  (131072 B)
    float* Esm = smem + 128 * 256; // [32][128]   (16384 B)

    const int tid = threadIdx.x;

    // Stage W1 rearranged: Wsm[k*256 + j]:
    //   j <  128 : W1[k*128 + j]             (A half)
    //   j >= 128 : W1[(128+k)*128 + (j-128)] (B half)
    for (int idx = tid; idx < 128 * 256; idx += PT) {
        int k = idx >> 8, j = idx & 255;
        float v = (j < 128) ? __ldg(&W1[k * 128 + j])
                            : __ldg(&W1[(128 + k) * 128 + (j - 128)]);
        Wsm[idx] = v;
    }

    const int cq = tid & 63;          // col quad: cols cq*4 .. cq*4+3
    const int r4 = (tid >> 6) * 4;    // row base within tile (0..28)
    float4 badd = make_float4(0.f, 0.f, 0.f, 0.f);
    if (cq * 4 < 128) badd = __ldg((const float4*)b1 + cq);

    const float4* W4 = (const float4*)Wsm;   // row length 64 float4
    const float4* E4 = (const float4*)Esm;   // row length 32 float4

    int nTiles = (nNodes + TROWS - 1) / TROWS;
    for (int tile = blockIdx.x; tile < nTiles; tile += gridDim.x) {
        int row0 = tile * TROWS;
        __syncthreads();   // protect Esm reuse from previous iteration
        for (int idx = tid; idx < TROWS * 32; idx += PT) {
            int r = idx >> 5, kq = idx & 31;
            int row = row0 + r;
            float4 v = (row < nNodes)
                ? __ldg((const float4*)emb + (size_t)row * 32 + kq)
                : make_float4(0.f, 0.f, 0.f, 0.f);
            ((float4*)Esm)[r * 32 + kq] = v;
        }
        __syncthreads();

        float acc[4][4];
        #pragma unroll
        for (int r = 0; r < 4; r++)
            #pragma unroll
            for (int j = 0; j < 4; j++) acc[r][j] = 0.f;

        #pragma unroll 4
        for (int k = 0; k < 128; k += 4) {
            float er[4][4];
            #pragma unroll
            for (int r = 0; r < 4; r++) {
                float4 t = E4[(r4 + r) * 32 + (k >> 2)];
                er[r][0] = t.x; er[r][1] = t.y; er[r][2] = t.z; er[r][3] = t.w;
            }
            #pragma unroll
            for (int kk = 0; kk < 4; kk++) {
                float4 wv = W4[(k + kk) * 64 + cq];
                #pragma unroll
                for (int r = 0; r < 4; r++) {
                    float e = er[r][kk];
                    acc[r][0] = fmaf(e, wv.x, acc[r][0]);
                    acc[r][1] = fmaf(e, wv.y, acc[r][1]);
                    acc[r][2] = fmaf(e, wv.z, acc[r][2]);
                    acc[r][3] = fmaf(e, wv.w, acc[r][3]);
                }
            }
        }

        #pragma unroll
        for (int r = 0; r < 4; r++) {
            int row = row0 + r4 + r;
            if (row < nNodes) {
                float4 o = make_float4(acc[r][0] + badd.x, acc[r][1] + badd.y,
                                       acc[r][2] + badd.z, acc[r][3] + badd.w);
                *((float4*)(d_AB + (size_t)row * 256) + cq) = o;
            }
        }
    }
}

// ---------------------------------------------------------------------------
// edge kernel: warp per edge (2 in flight); block max -> d_partial
__global__ __launch_bounds__(256)
void k_edges(const float* __restrict__ W2, const float* __restrict__ b2, int E) {
    const int lane = threadIdx.x & 31;
    const int wl   = threadIdx.x >> 5;
    const int gw = (blockIdx.x * blockDim.x + threadIdx.x) >> 5;
    const int nw = (gridDim.x * blockDim.x) >> 5;

    float4 w2 = __ldg((const float4*)W2 + lane);
    float bb2 = __ldg(b2);
    float lmax = -3.402823466e38f;

    const int* src = d_idx;
    const int* tgt = d_idx + E;

    for (int e0 = gw; e0 < E; e0 += 2 * nw) {
        int e1 = e0 + nw;
        bool has1 = (e1 < E);
        int s0 = src[e0], t0 = tgt[e0];
        int s1 = has1 ? src[e1] : s0;
        int t1 = has1 ? tgt[e1] : t0;

        float4 a0 = __ldg((const float4*)(d_AB + (size_t)s0 * 256) + lane);
        float4 c0 = __ldg((const float4*)(d_AB + (size_t)t0 * 256 + 128) + lane);
        float4 a1 = __ldg((const float4*)(d_AB + (size_t)s1 * 256) + lane);
        float4 c1 = __ldg((const float4*)(d_AB + (size_t)t1 * 256 + 128) + lane);

        float acc0 = fmaxf(a0.x + c0.x, 0.f) * w2.x + fmaxf(a0.y + c0.y, 0.f) * w2.y
                   + fmaxf(a0.z + c0.z, 0.f) * w2.z + fmaxf(a0.w + c0.w, 0.f) * w2.w;
        float acc1 = fmaxf(a1.x + c1.x, 0.f) * w2.x + fmaxf(a1.y + c1.y, 0.f) * w2.y
                   + fmaxf(a1.z + c1.z, 0.f) * w2.z + fmaxf(a1.w + c1.w, 0.f) * w2.w;

        #pragma unroll
        for (int o = 16; o; o >>= 1) {
            acc0 += __shfl_xor_sync(0xffffffffu, acc0, o);
            acc1 += __shfl_xor_sync(0xffffffffu, acc1, o);
        }
        if (lane == 0) {
            float lg0 = acc0 + bb2;
            d_logits[e0] = lg0;
            lmax = fmaxf(lmax, lg0);
            if (has1) {
                float lg1 = acc1 + bb2;
                d_logits[e1] = lg1;
                lmax = fmaxf(lmax, lg1);
            }
        }
    }

    __shared__ float sm[8];
    #pragma unroll
    for (int o = 16; o; o >>= 1) lmax = fmaxf(lmax, __shfl_xor_sync(0xffffffffu, lmax, o));
    if (lane == 0) sm[wl] = lmax;
    __syncthreads();
    if (threadIdx.x == 0) {
        float m = sm[0];
        #pragma unroll
        for (int i = 1; i < 8; i++) m = fmaxf(m, sm[i]);
        d_partial[blockIdx.x] = m;
    }
}

__global__ void k_reduce_max(int n) {
    __shared__ float sm[32];
    float m = -3.402823466e38f;
    for (int i = threadIdx.x; i < n; i += blockDim.x) m = fmaxf(m, d_partial[i]);
    #pragma unroll
    for (int o = 16; o; o >>= 1) m = fmaxf(m, __shfl_xor_sync(0xffffffffu, m, o));
    if ((threadIdx.x & 31) == 0) sm[threadIdx.x >> 5] = m;
    __syncthreads();
    if (threadIdx.x < 32) {
        int nwarp = (blockDim.x + 31) >> 5;
        float v = (threadIdx.x < nwarp) ? sm[threadIdx.x] : -3.402823466e38f;
        #pragma unroll
        for (int o = 16; o; o >>= 1) v = fmaxf(v, __shfl_xor_sync(0xffffffffu, v, o));
        if (threadIdx.x == 0) d_scalars[0] = v;
    }
}

// sum pass: accumulate sum of exp(logit - gmax), no writes of exp
__global__ __launch_bounds__(256)
void k_expsum(int E) {
    float gmax = d_scalars[0];
    float s = 0.f;
    int stride = gridDim.x * blockDim.x;
    for (int i = blockIdx.x * blockDim.x + threadIdx.x; i < E; i += stride)
        s += expf(d_logits[i] - gmax);
    __shared__ float sm[8];
    #pragma unroll
    for (int o = 16; o; o >>= 1) s += __shfl_xor_sync(0xffffffffu, s, o);
    if ((threadIdx.x & 31) == 0) sm[threadIdx.x >> 5] = s;
    __syncthreads();
    if (threadIdx.x == 0) {
        float t = 0.f;
        #pragma unroll
        for (int i = 0; i < 8; i++) t += sm[i];
        d_partial[blockIdx.x] = t;
    }
}

__global__ void k_reduce_sum(int n) {
    __shared__ float sm[32];
    float s = 0.f;
    for (int i = threadIdx.x; i < n; i += blockDim.x) s += d_partial[i];
    #pragma unroll
    for (int o = 16; o; o >>= 1) s += __shfl_xor_sync(0xffffffffu, s, o);
    if ((threadIdx.x & 31) == 0) sm[threadIdx.x >> 5] = s;
    __syncthreads();
    if (threadIdx.x < 32) {
        int nwarp = (blockDim.x + 31) >> 5;
        float v = (threadIdx.x < nwarp) ? sm[threadIdx.x] : 0.f;
        #pragma unroll
        for (int o = 16; o; o >>= 1) v += __shfl_xor_sync(0xffffffffu, v, o);
        if (threadIdx.x == 0) d_scalars[1] = 1.f / v;
    }
}

// write pass: out = exp(logit - gmax) * inv_sum
__global__ __launch_bounds__(256)
void k_write(float* __restrict__ out, int E) {
    float gmax = d_scalars[0];
    float inv  = d_scalars[1];
    int stride = gridDim.x * blockDim.x;
    for (int i = blockIdx.x * blockDim.x + threadIdx.x; i < E; i += stride)
        out[i] = expf(d_logits[i] - gmax) * inv;
}

// ---------------------------------------------------------------------------
extern "C" void kernel_launch(void* const* d_in, const int* in_sizes, int n_in,
                              void* d_out, int out_size) {
    const float*    emb  = (const float*)d_in[0];
    const unsigned* lm32 = (const unsigned*)d_in[1];
    const float*    W1   = (const float*)d_in[2];
    const float*    b1   = (const float*)d_in[3];
    const float*    W2   = (const float*)d_in[4];
    const float*    b2   = (const float*)d_in[5];
    float* out = (float*)d_out;

    int nNodes = in_sizes[0] / HID;
    int E = in_sizes[1] / 2;
    if (nNodes > NMAX) nNodes = NMAX;
    if (E > EMAX) E = EMAX;

    const int SMEM = (128 * 256 + TROWS * 128) * (int)sizeof(float);  // 147456
    cudaFuncSetAttribute(k_precompute, cudaFuncAttributeMaxDynamicSharedMemorySize, SMEM);

    k_init<<<1, 1>>>();
    k_detect<<<256, 256>>>(lm32, 2 * E);
    k_convert<<<512, 256>>>(lm32, 2 * E);
    k_precompute<<<148, PT, SMEM>>>(emb, W1, b1, nNodes);
    k_edges<<<592, 256>>>(W2, b2, E);
    k_reduce_max<<<1, 1024>>>(592);
    k_expsum<<<1024, 256>>>(E);
    k_reduce_sum<<<1, 1024>>>(1024);
    k_write<<<1024, 256>>>(out, E);
}

// round 4
// speedup vs baseline: 1.1131x; 1.0266x over previous
#include <cuda_runtime.h>

// ============================================================================
// RelationalPolicyHead: probs = softmax( relu([emb[s],emb[t]] @ W1 + b1) @ W2 + b2 )
//
// Factorization: A[n] = emb[n] @ W1[:128] + b1 ; B[n] = emb[n] @ W1[128:]
//   logit[e] = sum_j relu(A[s_e][j] + B[t_e][j]) * W2[j] + b2
// Precompute kernel uses packed fp32 FFMA2 (fma.rn.f32x2, Blackwell) to double
// fp32 FMA throughput, 8x4 register tiles to cut shared-crossbar traffic.
// ============================================================================

#define HID 128
#define NMAX 100000
#define EMAX 1000000

__device__ float d_AB[(size_t)NMAX * 256];      // per node: [A(128) | B(128)]
__device__ float d_logits[EMAX];
__device__ float d_partial[2048];               // edge-block maxima
__device__ float d_partial2[2048];              // exp-block sums
__device__ unsigned d_flag;                     // index dtype detection

typedef unsigned long long u64;

__device__ __forceinline__ u64 ffma2(u64 a, u64 b, u64 c) {
    u64 d;
    asm("fma.rn.f32x2 %0, %1, %2, %3;" : "=l"(d) : "l"(a), "l"(b), "l"(c));
    return d;
}
__device__ __forceinline__ u64 pack2(float lo, float hi) {
    u64 d;
    asm("mov.b64 %0, {%1, %2};" : "=l"(d) : "f"(lo), "f"(hi));
    return d;
}
__device__ __forceinline__ void unpack2(u64 v, float& lo, float& hi) {
    asm("mov.b64 {%0, %1}, %2;" : "=f"(lo), "=f"(hi) : "l"(v));
}

// ---------------------------------------------------------------------------
__global__ void k_init() { d_flag = 0u; }

// detect index dtype: probe ONLY first 2E words (exist in both layouts).
// int64 -> odd words are hi-halves of first E entries -> all zero.
__global__ void k_detect(const unsigned* __restrict__ lm32, int nwords) {
    unsigned acc = 0;
    int stride = gridDim.x * blockDim.x;
    int npairs = nwords >> 1;
    for (int i = blockIdx.x * blockDim.x + threadIdx.x; i < npairs; i += stride)
        acc |= lm32[2 * i + 1];
    #pragma unroll
    for (int o = 16; o; o >>= 1) acc |= __shfl_xor_sync(0xffffffffu, acc, o);
    if ((threadIdx.x & 31) == 0 && acc) atomicOr(&d_flag, acc);
}

// ---------------------------------------------------------------------------
// precompute AB = emb @ [W1a | W1b] (+b1 on A half)
// 512 threads, tile 64 rows x 256 cols, thread tile 8 rows x 4 cols (2 f32x2
// col-pairs). W staged once per SM (128 KB), Esm 32 KB -> 160 KB smem.
#define TROWS 64
#define PT 512
__global__ __launch_bounds__(PT, 1)
void k_precompute(const float* __restrict__ emb,
                  const float* __restrict__ W1,
                  const float* __restrict__ b1,
                  int nNodes) {
    extern __shared__ float smem[];
    float* Wsm = smem;               // [128][256] floats (131072 B)
    float* Esm = smem + 128 * 256;   // [64][128] floats  (32768 B)

    const int tid = threadIdx.x;

    // Stage W1 rearranged: Wsm[k*256 + j]:
    //   j <  128 : W1[k*128 + j]             (A half)
    //   j >= 128 : W1[(128+k)*128 + (j-128)] (B half)
    for (int idx = tid; idx < 128 * 256; idx += PT) {
        int k = idx >> 8, j = idx & 255;
        float v = (j < 128) ? __ldg(&W1[k * 128 + j])
                            : __ldg(&W1[(128 + k) * 128 + (j - 128)]);
        Wsm[idx] = v;
    }

    const int cq = tid & 63;          // col quad: cols cq*4 .. cq*4+3
    const int rb = (tid >> 6) * 8;    // row base within tile (0,8,...,56)
    float4 badd = make_float4(0.f, 0.f, 0.f, 0.f);
    if (cq * 4 < 128) badd = __ldg((const float4*)b1 + cq);

    const ulonglong2* W2v = (const ulonglong2*)Wsm;  // row = 64 ulonglong2
    const float4* E4 = (const float4*)Esm;           // row = 32 float4

    int nTiles = (nNodes + TROWS - 1) / TROWS;
    for (int tile = blockIdx.x; tile < nTiles; tile += gridDim.x) {
        int row0 = tile * TROWS;
        __syncthreads();   // protect Esm reuse from previous iteration
        for (int idx = tid; idx < TROWS * 32; idx += PT) {
            int r = idx >> 5, kq = idx & 31;
            int row = row0 + r;
            float4 v = (row < nNodes)
                ? __ldg((const float4*)emb + (size_t)row * 32 + kq)
                : make_float4(0.f, 0.f, 0.f, 0.f);
            ((float4*)Esm)[r * 32 + kq] = v;
        }
        __syncthreads();

        u64 acc[8][2];
        #pragma unroll
        for (int r = 0; r < 8; r++) { acc[r][0] = 0ull; acc[r][1] = 0ull; }

        #pragma unroll 2
        for (int k = 0; k < 128; k += 4) {
            float4 t[8];
            #pragma unroll
            for (int r = 0; r < 8; r++)
                t[r] = E4[(rb + r) * 32 + (k >> 2)];   // warp-broadcast
            #pragma unroll
            for (int kk = 0; kk < 4; kk++) {
                ulonglong2 w = W2v[(k + kk) * 64 + cq];  // LDS.128 -> 2 f32x2
                #pragma unroll
                for (int r = 0; r < 8; r++) {
                    float e = ((const float*)&t[r])[kk];
                    u64 e2 = pack2(e, e);
                    acc[r][0] = ffma2(e2, w.x, acc[r][0]);
                    acc[r][1] = ffma2(e2, w.y, acc[r][1]);
                }
            }
        }

        #pragma unroll
        for (int r = 0; r < 8; r++) {
            int row = row0 + rb + r;
            if (row < nNodes) {
                float x0, x1, x2, x3;
                unpack2(acc[r][0], x0, x1);
                unpack2(acc[r][1], x2, x3);
                float4 o = make_float4(x0 + badd.x, x1 + badd.y,
                                       x2 + badd.z, x3 + badd.w);
                *((float4*)(d_AB + (size_t)row * 256) + cq) = o;
            }
        }
    }
}

// ---------------------------------------------------------------------------
// edge kernel: warp per edge (2 in flight); reads RAW index buffer (dtype
// branch on d_flag); block max -> d_partial
__global__ __launch_bounds__(256)
void k_edges(const unsigned* __restrict__ lm32,
             const float* __restrict__ W2, const float* __restrict__ b2, int E) {
    const int lane = threadIdx.x & 31;
    const int wl   = threadIdx.x >> 5;
    const int gw = (blockIdx.x * blockDim.x + threadIdx.x) >> 5;
    const int nw = (gridDim.x * blockDim.x) >> 5;
    const bool is64 = (d_flag == 0u);

    float4 w2 = __ldg((const float4*)W2 + lane);
    float bb2 = __ldg(b2);
    float lmax = -3.402823466e38f;

    for (int e0 = gw; e0 < E; e0 += 2 * nw) {
        int e1 = e0 + nw;
        bool has1 = (e1 < E);
        int ee1 = has1 ? e1 : e0;
        int s0, t0, s1, t1;
        if (is64) {
            s0 = (int)lm32[2 * e0];       t0 = (int)lm32[2 * (E + e0)];
            s1 = (int)lm32[2 * ee1];      t1 = (int)lm32[2 * (E + ee1)];
        } else {
            s0 = (int)lm32[e0];           t0 = (int)lm32[E + e0];
            s1 = (int)lm32[ee1];          t1 = (int)lm32[E + ee1];
        }

        float4 a0 = __ldg((const float4*)(d_AB + (size_t)s0 * 256) + lane);
        float4 c0 = __ldg((const float4*)(d_AB + (size_t)t0 * 256 + 128) + lane);
        float4 a1 = __ldg((const float4*)(d_AB + (size_t)s1 * 256) + lane);
        float4 c1 = __ldg((const float4*)(d_AB + (size_t)t1 * 256 + 128) + lane);

        float acc0 = fmaxf(a0.x + c0.x, 0.f) * w2.x + fmaxf(a0.y + c0.y, 0.f) * w2.y
                   + fmaxf(a0.z + c0.z, 0.f) * w2.z + fmaxf(a0.w + c0.w, 0.f) * w2.w;
        float acc1 = fmaxf(a1.x + c1.x, 0.f) * w2.x + fmaxf(a1.y + c1.y, 0.f) * w2.y
                   + fmaxf(a1.z + c1.z, 0.f) * w2.z + fmaxf(a1.w + c1.w, 0.f) * w2.w;

        #pragma unroll
        for (int o = 16; o; o >>= 1) {
            acc0 += __shfl_xor_sync(0xffffffffu, acc0, o);
            acc1 += __shfl_xor_sync(0xffffffffu, acc1, o);
        }
        if (lane == 0) {
            float lg0 = acc0 + bb2;
            d_logits[e0] = lg0;
            lmax = fmaxf(lmax, lg0);
            if (has1) {
                float lg1 = acc1 + bb2;
                d_logits[e1] = lg1;
                lmax = fmaxf(lmax, lg1);
            }
        }
    }

    __shared__ float sm[8];
    #pragma unroll
    for (int o = 16; o; o >>= 1) lmax = fmaxf(lmax, __shfl_xor_sync(0xffffffffu, lmax, o));
    if (lane == 0) sm[wl] = lmax;
    __syncthreads();
    if (threadIdx.x == 0) {
        float m = sm[0];
        #pragma unroll
        for (int i = 1; i < 8; i++) m = fmaxf(m, sm[i]);
        d_partial[blockIdx.x] = m;
    }
}

// ---------------------------------------------------------------------------
// expsum: every block redundantly reduces the 592 edge-block maxima (saves a
// launch), then accumulates sum of exp(logit - gmax) -> d_partial2[block]
__global__ __launch_bounds__(256)
void k_expsum(int E, int nmax) {
    __shared__ float red[8];
    __shared__ float s_gmax;
    // inline max-reduce
    float m = -3.402823466e38f;
    for (int i = threadIdx.x; i < nmax; i += blockDim.x) m = fmaxf(m, d_partial[i]);
    #pragma unroll
    for (int o = 16; o; o >>= 1) m = fmaxf(m, __shfl_xor_sync(0xffffffffu, m, o));
    if ((threadIdx.x & 31) == 0) red[threadIdx.x >> 5] = m;
    __syncthreads();
    if (threadIdx.x == 0) {
        float v = red[0];
        #pragma unroll
        for (int i = 1; i < 8; i++) v = fmaxf(v, red[i]);
        s_gmax = v;
    }
    __syncthreads();
    float gmax = s_gmax;

    float s = 0.f;
    int stride = gridDim.x * blockDim.x;
    for (int i = blockIdx.x * blockDim.x + threadIdx.x; i < E; i += stride)
        s += expf(d_logits[i] - gmax);
    __syncthreads();
    #pragma unroll
    for (int o = 16; o; o >>= 1) s += __shfl_xor_sync(0xffffffffu, s, o);
    if ((threadIdx.x & 31) == 0) red[threadIdx.x >> 5] = s;
    __syncthreads();
    if (threadIdx.x == 0) {
        float t = 0.f;
        #pragma unroll
        for (int i = 0; i < 8; i++) t += red[i];
        d_partial2[blockIdx.x] = t;
    }
}

// write pass: every block redundantly reduces the exp-sums and gmax, then
// out = exp(logit - gmax) * inv_sum
__global__ __launch_bounds__(256)
void k_write(float* __restrict__ out, int E, int nmax, int nsum) {
    __shared__ float red[8];
    __shared__ float s_gmax, s_inv;
    float m = -3.402823466e38f;
    for (int i = threadIdx.x; i < nmax; i += blockDim.x) m = fmaxf(m, d_partial[i]);
    #pragma unroll
    for (int o = 16; o; o >>= 1) m = fmaxf(m, __shfl_xor_sync(0xffffffffu, m, o));
    if ((threadIdx.x & 31) == 0) red[threadIdx.x >> 5] = m;
    __syncthreads();
    if (threadIdx.x == 0) {
        float v = red[0];
        #pragma unroll
        for (int i = 1; i < 8; i++) v = fmaxf(v, red[i]);
        s_gmax = v;
    }
    __syncthreads();
    float gmax = s_gmax;
    __syncthreads();

    float s = 0.f;
    for (int i = threadIdx.x; i < nsum; i += blockDim.x) s += d_partial2[i];
    #pragma unroll
    for (int o = 16; o; o >>= 1) s += __shfl_xor_sync(0xffffffffu, s, o);
    if ((threadIdx.x & 31) == 0) red[threadIdx.x >> 5] = s;
    __syncthreads();
    if (threadIdx.x == 0) {
        float t = 0.f;
        #pragma unroll
        for (int i = 0; i < 8; i++) t += red[i];
        s_inv = 1.f / t;
    }
    __syncthreads();
    float inv = s_inv;

    int stride = gridDim.x * blockDim.x;
    for (int i = blockIdx.x * blockDim.x + threadIdx.x; i < E; i += stride)
        out[i] = expf(d_logits[i] - gmax) * inv;
}

// ---------------------------------------------------------------------------
extern "C" void kernel_launch(void* const* d_in, const int* in_sizes, int n_in,
                              void* d_out, int out_size) {
    const float*    emb  = (const float*)d_in[0];
    const unsigned* lm32 = (const unsigned*)d_in[1];
    const float*    W1   = (const float*)d_in[2];
    const float*    b1   = (const float*)d_in[3];
    const float*    W2   = (const float*)d_in[4];
    const float*    b2   = (const float*)d_in[5];
    float* out = (float*)d_out;

    int nNodes = in_sizes[0] / HID;
    int E = in_sizes[1] / 2;
    if (nNodes > NMAX) nNodes = NMAX;
    if (E > EMAX) E = EMAX;

    const int SMEM = (128 * 256 + TROWS * 128) * (int)sizeof(float);  // 163840
    cudaFuncSetAttribute(k_precompute, cudaFuncAttributeMaxDynamicSharedMemorySize, SMEM);

    k_init<<<1, 1>>>();
    k_detect<<<256, 256>>>(lm32, 2 * E);
    k_precompute<<<148, PT, SMEM>>>(emb, W1, b1, nNodes);
    k_edges<<<592, 256>>>(lm32, W2, b2, E);
    k_expsum<<<1024, 256>>>(E, 592);
    k_write<<<1024, 256>>>(out, E, 592, 1024);
}

// round 6
// speedup vs baseline: 1.3298x; 1.1947x over previous
#include <cuda_runtime.h>

// ============================================================================
// RelationalPolicyHead: probs = softmax( relu([emb[s],emb[t]] @ W1 + b1) @ W2 + b2 )
//
// Factorization: A[n] = emb[n] @ W1[:128] + b1 ; B[n] = emb[n] @ W1[128:]
//   logit[e] = sum_j relu(A[s_e][j] + B[t_e][j]) * W2[j] + b2
// AB table (102 MB) held L2-resident via createpolicy evict_last cache hints;
// all streaming traffic (indices, logits, probs) uses evict-first (.cs).
// ============================================================================

#define HID 128
#define NMAX 100000
#define EMAX 1000000

__device__ float d_AB[(size_t)NMAX * 256];      // per node: [A(128) | B(128)]
__device__ float d_logits[EMAX];
__device__ float d_partial[2048];               // edge-block maxima
__device__ float d_partial2[2048];              // exp-block sums
__device__ unsigned d_flag;                     // index dtype detection

typedef unsigned long long u64;

__device__ __forceinline__ u64 ffma2(u64 a, u64 b, u64 c) {
    u64 d;
    asm("fma.rn.f32x2 %0, %1, %2, %3;" : "=l"(d) : "l"(a), "l"(b), "l"(c));
    return d;
}
__device__ __forceinline__ u64 pack2(float lo, float hi) {
    u64 d;
    asm("mov.b64 %0, {%1, %2};" : "=l"(d) : "f"(lo), "f"(hi));
    return d;
}
__device__ __forceinline__ void unpack2(u64 v, float& lo, float& hi) {
    asm("mov.b64 {%0, %1}, %2;" : "=f"(lo), "=f"(hi) : "l"(v));
}
// L2 evict-last access policy (keep AB table resident in L2)
__device__ __forceinline__ u64 mkpolicy_el() {
    u64 p;
    asm("createpolicy.fractional.L2::evict_last.b64 %0, 1.0;" : "=l"(p));
    return p;
}
__device__ __forceinline__ float4 ldg_el(const float* p, u64 pol) {
    float4 v;
    asm("ld.global.nc.L2::cache_hint.v4.f32 {%0,%1,%2,%3}, [%4], %5;"
        : "=f"(v.x), "=f"(v.y), "=f"(v.z), "=f"(v.w) : "l"(p), "l"(pol));
    return v;
}

// ---------------------------------------------------------------------------
__global__ void k_init() { d_flag = 0u; }

// detect index dtype: probe ONLY first 2E words (exist in both layouts).
// int64 -> odd words are hi-halves of first E entries -> all zero.
__global__ void k_detect(const unsigned* __restrict__ lm32, int nwords) {
    unsigned acc = 0;
    int stride = gridDim.x * blockDim.x;
    int npairs = nwords >> 1;
    for (int i = blockIdx.x * blockDim.x + threadIdx.x; i < npairs; i += stride)
        acc |= __ldcs(&lm32[2 * i + 1]);
    #pragma unroll
    for (int o = 16; o; o >>= 1) acc |= __shfl_xor_sync(0xffffffffu, acc, o);
    if ((threadIdx.x & 31) == 0 && acc) atomicOr(&d_flag, acc);
}

// ---------------------------------------------------------------------------
// precompute AB = emb @ [W1a | W1b] (+b1 on A half)
// 512 threads, tile 64 rows x 256 cols, thread tile 8 rows x 4 cols via
// packed fp32 FFMA2. W staged once per SM (128 KB), Esm 32 KB.
#define TROWS 64
#define PT 512
__global__ __launch_bounds__(PT, 1)
void k_precompute(const float* __restrict__ emb,
                  const float* __restrict__ W1,
                  const float* __restrict__ b1,
                  int nNodes) {
    extern __shared__ float smem[];
    float* Wsm = smem;               // [128][256] floats (131072 B)
    float* Esm = smem + 128 * 256;   // [64][128] floats  (32768 B)

    const int tid = threadIdx.x;

    for (int idx = tid; idx < 128 * 256; idx += PT) {
        int k = idx >> 8, j = idx & 255;
        float v = (j < 128) ? __ldg(&W1[k * 128 + j])
                            : __ldg(&W1[(128 + k) * 128 + (j - 128)]);
        Wsm[idx] = v;
    }

    const int cq = tid & 63;          // col quad
    const int rb = (tid >> 6) * 8;    // row base (0,8,...,56)
    float4 badd = make_float4(0.f, 0.f, 0.f, 0.f);
    if (cq * 4 < 128) badd = __ldg((const float4*)b1 + cq);

    const ulonglong2* W2v = (const ulonglong2*)Wsm;
    const float4* E4 = (const float4*)Esm;

    int nTiles = (nNodes + TROWS - 1) / TROWS;
    for (int tile = blockIdx.x; tile < nTiles; tile += gridDim.x) {
        int row0 = tile * TROWS;
        __syncthreads();
        for (int idx = tid; idx < TROWS * 32; idx += PT) {
            int r = idx >> 5, kq = idx & 31;
            int row = row0 + r;
            float4 v = (row < nNodes)
                ? __ldcs((const float4*)emb + (size_t)row * 32 + kq)   // stream emb
                : make_float4(0.f, 0.f, 0.f, 0.f);
            ((float4*)Esm)[r * 32 + kq] = v;
        }
        __syncthreads();

        u64 acc[8][2];
        #pragma unroll
        for (int r = 0; r < 8; r++) { acc[r][0] = 0ull; acc[r][1] = 0ull; }

        #pragma unroll 2
        for (int k = 0; k < 128; k += 4) {
            float4 t[8];
            #pragma unroll
            for (int r = 0; r < 8; r++)
                t[r] = E4[(rb + r) * 32 + (k >> 2)];
            #pragma unroll
            for (int kk = 0; kk < 4; kk++) {
                ulonglong2 w = W2v[(k + kk) * 64 + cq];
                #pragma unroll
                for (int r = 0; r < 8; r++) {
                    float e = ((const float*)&t[r])[kk];
                    u64 e2 = pack2(e, e);
                    acc[r][0] = ffma2(e2, w.x, acc[r][0]);
                    acc[r][1] = ffma2(e2, w.y, acc[r][1]);
                }
            }
        }

        #pragma unroll
        for (int r = 0; r < 8; r++) {
            int row = row0 + rb + r;
            if (row < nNodes) {
                float x0, x1, x2, x3;
                unpack2(acc[r][0], x0, x1);
                unpack2(acc[r][1], x2, x3);
                float4 o = make_float4(x0 + badd.x, x1 + badd.y,
                                       x2 + badd.z, x3 + badd.w);
                *((float4*)(d_AB + (size_t)row * 256) + cq) = o;
            }
        }
    }
}

// ---------------------------------------------------------------------------
// edge kernel: warp per edge (2 in flight), 8 blocks/SM for full occupancy.
__global__ __launch_bounds__(256, 8)
void k_edges(const unsigned* __restrict__ lm32,
             const float* __restrict__ W2, const float* __restrict__ b2, int E) {
    const int lane = threadIdx.x & 31;
    const int wl   = threadIdx.x >> 5;
    const int gw = (blockIdx.x * blockDim.x + threadIdx.x) >> 5;
    const int nw = (gridDim.x * blockDim.x) >> 5;
    const bool is64 = (d_flag == 0u);
    const u64 pol = mkpolicy_el();

    float4 w2 = __ldg((const float4*)W2 + lane);
    float bb2 = __ldg(b2);
    float lmax = -3.402823466e38f;

    for (int e0 = gw; e0 < E; e0 += 2 * nw) {
        int e1 = e0 + nw;
        bool has1 = (e1 < E);
        int ee1 = has1 ? e1 : e0;
        int s0, t0, s1, t1;
        if (is64) {
            s0 = (int)__ldcs(&lm32[2 * e0]);  t0 = (int)__ldcs(&lm32[2 * (E + e0)]);
            s1 = (int)__ldcs(&lm32[2 * ee1]); t1 = (int)__ldcs(&lm32[2 * (E + ee1)]);
        } else {
            s0 = (int)__ldcs(&lm32[e0]);      t0 = (int)__ldcs(&lm32[E + e0]);
            s1 = (int)__ldcs(&lm32[ee1]);     t1 = (int)__ldcs(&lm32[E + ee1]);
        }

        float4 a0 = ldg_el(d_AB + (size_t)s0 * 256 + lane * 4, pol);
        float4 c0 = ldg_el(d_AB + (size_t)t0 * 256 + 128 + lane * 4, pol);
        float4 a1 = ldg_el(d_AB + (size_t)s1 * 256 + lane * 4, pol);
        float4 c1 = ldg_el(d_AB + (size_t)t1 * 256 + 128 + lane * 4, pol);

        float acc0 = fmaxf(a0.x + c0.x, 0.f) * w2.x + fmaxf(a0.y + c0.y, 0.f) * w2.y
                   + fmaxf(a0.z + c0.z, 0.f) * w2.z + fmaxf(a0.w + c0.w, 0.f) * w2.w;
        float acc1 = fmaxf(a1.x + c1.x, 0.f) * w2.x + fmaxf(a1.y + c1.y, 0.f) * w2.y
                   + fmaxf(a1.z + c1.z, 0.f) * w2.z + fmaxf(a1.w + c1.w, 0.f) * w2.w;

        #pragma unroll
        for (int o = 16; o; o >>= 1) {
            acc0 += __shfl_xor_sync(0xffffffffu, acc0, o);
            acc1 += __shfl_xor_sync(0xffffffffu, acc1, o);
        }
        if (lane == 0) {
            float lg0 = acc0 + bb2;
            __stcs(&d_logits[e0], lg0);
            lmax = fmaxf(lmax, lg0);
            if (has1) {
                float lg1 = acc1 + bb2;
                __stcs(&d_logits[e1], lg1);
                lmax = fmaxf(lmax, lg1);
            }
        }
    }

    __shared__ float sm[8];
    #pragma unroll
    for (int o = 16; o; o >>= 1) lmax = fmaxf(lmax, __shfl_xor_sync(0xffffffffu, lmax, o));
    if (lane == 0) sm[wl] = lmax;
    __syncthreads();
    if (threadIdx.x == 0) {
        float m = sm[0];
        #pragma unroll
        for (int i = 1; i < 8; i++) m = fmaxf(m, sm[i]);
        d_partial[blockIdx.x] = m;
    }
}

// ---------------------------------------------------------------------------
// expsum: every block redundantly reduces the edge-block maxima, then
// accumulates sum of exp(logit - gmax) -> d_partial2[block]
__global__ __launch_bounds__(256)
void k_expsum(int E, int nmax) {
    __shared__ float red[8];
    __shared__ float s_gmax;
    float m = -3.402823466e38f;
    for (int i = threadIdx.x; i < nmax; i += blockDim.x) m = fmaxf(m, d_partial[i]);
    #pragma unroll
    for (int o = 16; o; o >>= 1) m = fmaxf(m, __shfl_xor_sync(0xffffffffu, m, o));
    if ((threadIdx.x & 31) == 0) red[threadIdx.x >> 5] = m;
    __syncthreads();
    if (threadIdx.x == 0) {
        float v = red[0];
        #pragma unroll
        for (int i = 1; i < 8; i++) v = fmaxf(v, red[i]);
        s_gmax = v;
    }
    __syncthreads();
    float gmax = s_gmax;

    float s = 0.f;
    int stride = gridDim.x * blockDim.x;
    for (int i = blockIdx.x * blockDim.x + threadIdx.x; i < E; i += stride)
        s += expf(__ldcs(&d_logits[i]) - gmax);
    __syncthreads();
    #pragma unroll
    for (int o = 16; o; o >>= 1) s += __shfl_xor_sync(0xffffffffu, s, o);
    if ((threadIdx.x & 31) == 0) red[threadIdx.x >> 5] = s;
    __syncthreads();
    if (threadIdx.x == 0) {
        float t = 0.f;
        #pragma unroll
        for (int i = 0; i < 8; i++) t += red[i];
        d_partial2[blockIdx.x] = t;
    }
}

// write pass: redundant scalar reductions per block, then
// out = exp(logit - gmax) * inv_sum
__global__ __launch_bounds__(256)
void k_write(float* __restrict__ out, int E, int nmax, int nsum) {
    __shared__ float red[8];
    __shared__ float s_gmax, s_inv;
    float m = -3.402823466e38f;
    for (int i = threadIdx.x; i < nmax; i += blockDim.x) m = fmaxf(m, d_partial[i]);
    #pragma unroll
    for (int o = 16; o; o >>= 1) m = fmaxf(m, __shfl_xor_sync(0xffffffffu, m, o));
    if ((threadIdx.x & 31) == 0) red[threadIdx.x >> 5] = m;
    __syncthreads();
    if (threadIdx.x == 0) {
        float v = red[0];
        #pragma unroll
        for (int i = 1; i < 8; i++) v = fmaxf(v, red[i]);
        s_gmax = v;
    }
    __syncthreads();
    float gmax = s_gmax;
    __syncthreads();

    float s = 0.f;
    for (int i = threadIdx.x; i < nsum; i += blockDim.x) s += d_partial2[i];
    #pragma unroll
    for (int o = 16; o; o >>= 1) s += __shfl_xor_sync(0xffffffffu, s, o);
    if ((threadIdx.x & 31) == 0) red[threadIdx.x >> 5] = s;
    __syncthreads();
    if (threadIdx.x == 0) {
        float t = 0.f;
        #pragma unroll
        for (int i = 0; i < 8; i++) t += red[i];
        s_inv = 1.f / t;
    }
    __syncthreads();
    float inv = s_inv;

    int stride = gridDim.x * blockDim.x;
    for (int i = blockIdx.x * blockDim.x + threadIdx.x; i < E; i += stride)
        __stcs(&out[i], expf(__ldcs(&d_logits[i]) - gmax) * inv);
}

// ---------------------------------------------------------------------------
extern "C" void kernel_launch(void* const* d_in, const int* in_sizes, int n_in,
                              void* d_out, int out_size) {
    const float*    emb  = (const float*)d_in[0];
    const unsigned* lm32 = (const unsigned*)d_in[1];
    const float*    W1   = (const float*)d_in[2];
    const float*    b1   = (const float*)d_in[3];
    const float*    W2   = (const float*)d_in[4];
    const float*    b2   = (const float*)d_in[5];
    float* out = (float*)d_out;

    int nNodes = in_sizes[0] / HID;
    int E = in_sizes[1] / 2;
    if (nNodes > NMAX) nNodes = NMAX;
    if (E > EMAX) E = EMAX;

    const int SMEM = (128 * 256 + TROWS * 128) * (int)sizeof(float);  // 163840
    cudaFuncSetAttribute(k_precompute, cudaFuncAttributeMaxDynamicSharedMemorySize, SMEM);

    k_init<<<1, 1>>>();
    k_detect<<<256, 256>>>(lm32, 2 * E);
    k_precompute<<<148, PT, SMEM>>>(emb, W1, b1, nNodes);
    k_edges<<<1184, 256>>>(lm32, W2, b2, E);     // 8 blocks/SM -> occ ~97%
    k_expsum<<<1024, 256>>>(E, 1184);
    k_write<<<1024, 256>>>(out, E, 1184, 1024);
}

// round 7
// speedup vs baseline: 1.4914x; 1.1215x over previous
#include <cuda_runtime.h>
#include <cuda_fp16.h>

// ============================================================================
// RelationalPolicyHead: probs = softmax( relu([emb[s],emb[t]] @ W1 + b1) @ W2 + b2 )
//
// Factorization: A[n] = emb[n] @ W1[:128] + b1 ; B[n] = emb[n] @ W1[128:]
//   logit[e] = sum_j relu(A[s_e][j] + B[t_e][j]) * W2[j] + b2
// AB table stored FP16 (51 MB -> fully L2-resident, half the gather traffic);
// all math in fp32. evict_last policy on gathers, .cs on streaming traffic.
// ============================================================================

#define HID 128
#define NMAX 100000
#define EMAX 1000000

__device__ __half d_AB16[(size_t)NMAX * 256];   // per node: [A(128) | B(128)] fp16
__device__ float d_logits[EMAX];
__device__ float d_partial[2048];               // edge-block maxima
__device__ float d_partial2[2048];              // exp-block sums
__device__ unsigned d_flag;                     // index dtype detection

typedef unsigned long long u64;

__device__ __forceinline__ u64 ffma2(u64 a, u64 b, u64 c) {
    u64 d;
    asm("fma.rn.f32x2 %0, %1, %2, %3;" : "=l"(d) : "l"(a), "l"(b), "l"(c));
    return d;
}
__device__ __forceinline__ u64 pack2(float lo, float hi) {
    u64 d;
    asm("mov.b64 %0, {%1, %2};" : "=l"(d) : "f"(lo), "f"(hi));
    return d;
}
__device__ __forceinline__ void unpack2(u64 v, float& lo, float& hi) {
    asm("mov.b64 {%0, %1}, %2;" : "=f"(lo), "=f"(hi) : "l"(v));
}
// L2 evict-last access policy (keep AB table resident in L2)
__device__ __forceinline__ u64 mkpolicy_el() {
    u64 p;
    asm("createpolicy.fractional.L2::evict_last.b64 %0, 1.0;" : "=l"(p));
    return p;
}
// 8-byte gather (4 halves) with evict_last hint
__device__ __forceinline__ uint2 ldg64_el(const __half* p, u64 pol) {
    uint2 v;
    asm("ld.global.nc.L2::cache_hint.v2.b32 {%0,%1}, [%2], %3;"
        : "=r"(v.x), "=r"(v.y) : "l"(p), "l"(pol));
    return v;
}
__device__ __forceinline__ float4 h4_to_f4(uint2 r) {
    __half2 h01 = *reinterpret_cast<__half2*>(&r.x);
    __half2 h23 = *reinterpret_cast<__half2*>(&r.y);
    float2 f01 = __half22float2(h01);
    float2 f23 = __half22float2(h23);
    return make_float4(f01.x, f01.y, f23.x, f23.y);
}

// ---------------------------------------------------------------------------
__global__ void k_init() { d_flag = 0u; }

// detect index dtype: probe ONLY first 2E words (exist in both layouts).
// int64 -> odd words are hi-halves of first E entries -> all zero.
__global__ void k_detect(const unsigned* __restrict__ lm32, int nwords) {
    unsigned acc = 0;
    int stride = gridDim.x * blockDim.x;
    int npairs = nwords >> 1;
    for (int i = blockIdx.x * blockDim.x + threadIdx.x; i < npairs; i += stride)
        acc |= __ldcs(&lm32[2 * i + 1]);
    #pragma unroll
    for (int o = 16; o; o >>= 1) acc |= __shfl_xor_sync(0xffffffffu, acc, o);
    if ((threadIdx.x & 31) == 0 && acc) atomicOr(&d_flag, acc);
}

// ---------------------------------------------------------------------------
// precompute AB = emb @ [W1a | W1b] (+b1 on A half), fp32 math, fp16 store.
// 512 threads, tile 64 rows x 256 cols, thread tile 8 rows x 4 cols via FFMA2.
#define TROWS 64
#define PT 512
__global__ __launch_bounds__(PT, 1)
void k_precompute(const float* __restrict__ emb,
                  const float* __restrict__ W1,
                  const float* __restrict__ b1,
                  int nNodes) {
    extern __shared__ float smem[];
    float* Wsm = smem;               // [128][256] floats (131072 B)
    float* Esm = smem + 128 * 256;   // [64][128] floats  (32768 B)

    const int tid = threadIdx.x;

    for (int idx = tid; idx < 128 * 256; idx += PT) {
        int k = idx >> 8, j = idx & 255;
        float v = (j < 128) ? __ldg(&W1[k * 128 + j])
                            : __ldg(&W1[(128 + k) * 128 + (j - 128)]);
        Wsm[idx] = v;
    }

    const int cq = tid & 63;          // col quad
    const int rb = (tid >> 6) * 8;    // row base (0,8,...,56)
    float4 badd = make_float4(0.f, 0.f, 0.f, 0.f);
    if (cq * 4 < 128) badd = __ldg((const float4*)b1 + cq);

    const ulonglong2* W2v = (const ulonglong2*)Wsm;
    const float4* E4 = (const float4*)Esm;

    int nTiles = (nNodes + TROWS - 1) / TROWS;
    for (int tile = blockIdx.x; tile < nTiles; tile += gridDim.x) {
        int row0 = tile * TROWS;
        __syncthreads();
        for (int idx = tid; idx < TROWS * 32; idx += PT) {
            int r = idx >> 5, kq = idx & 31;
            int row = row0 + r;
            float4 v = (row < nNodes)
                ? __ldcs((const float4*)emb + (size_t)row * 32 + kq)   // stream emb
                : make_float4(0.f, 0.f, 0.f, 0.f);
            ((float4*)Esm)[r * 32 + kq] = v;
        }
        __syncthreads();

        u64 acc[8][2];
        #pragma unroll
        for (int r = 0; r < 8; r++) { acc[r][0] = 0ull; acc[r][1] = 0ull; }

        #pragma unroll 2
        for (int k = 0; k < 128; k += 4) {
            float4 t[8];
            #pragma unroll
            for (int r = 0; r < 8; r++)
                t[r] = E4[(rb + r) * 32 + (k >> 2)];
            #pragma unroll
            for (int kk = 0; kk < 4; kk++) {
                ulonglong2 w = W2v[(k + kk) * 64 + cq];
                #pragma unroll
                for (int r = 0; r < 8; r++) {
                    float e = ((const float*)&t[r])[kk];
                    u64 e2 = pack2(e, e);
                    acc[r][0] = ffma2(e2, w.x, acc[r][0]);
                    acc[r][1] = ffma2(e2, w.y, acc[r][1]);
                }
            }
        }

        #pragma unroll
        for (int r = 0; r < 8; r++) {
            int row = row0 + rb + r;
            if (row < nNodes) {
                float x0, x1, x2, x3;
                unpack2(acc[r][0], x0, x1);
                unpack2(acc[r][1], x2, x3);
                __half2 p01 = __floats2half2_rn(x0 + badd.x, x1 + badd.y);
                __half2 p23 = __floats2half2_rn(x2 + badd.z, x3 + badd.w);
                uint2 o;
                o.x = *reinterpret_cast<unsigned*>(&p01);
                o.y = *reinterpret_cast<unsigned*>(&p23);
                *((uint2*)(d_AB16 + (size_t)row * 256) + cq) = o;
            }
        }
    }
}

// ---------------------------------------------------------------------------
// edge kernel: warp per edge (2 in flight), 8 blocks/SM.
// Gathers are LDG.64 (4 halves A + 4 halves B per lane), math in fp32.
__global__ __launch_bounds__(256, 8)
void k_edges(const unsigned* __restrict__ lm32,
             const float* __restrict__ W2, const float* __restrict__ b2, int E) {
    const int lane = threadIdx.x & 31;
    const int wl   = threadIdx.x >> 5;
    const int gw = (blockIdx.x * blockDim.x + threadIdx.x) >> 5;
    const int nw = (gridDim.x * blockDim.x) >> 5;
    const bool is64 = (d_flag == 0u);
    const u64 pol = mkpolicy_el();

    float4 w2 = __ldg((const float4*)W2 + lane);
    float bb2 = __ldg(b2);
    float lmax = -3.402823466e38f;

    for (int e0 = gw; e0 < E; e0 += 2 * nw) {
        int e1 = e0 + nw;
        bool has1 = (e1 < E);
        int ee1 = has1 ? e1 : e0;
        int s0, t0, s1, t1;
        if (is64) {
            s0 = (int)__ldcs(&lm32[2 * e0]);  t0 = (int)__ldcs(&lm32[2 * (E + e0)]);
            s1 = (int)__ldcs(&lm32[2 * ee1]); t1 = (int)__ldcs(&lm32[2 * (E + ee1)]);
        } else {
            s0 = (int)__ldcs(&lm32[e0]);      t0 = (int)__ldcs(&lm32[E + e0]);
            s1 = (int)__ldcs(&lm32[ee1]);     t1 = (int)__ldcs(&lm32[E + ee1]);
        }

        uint2 ra0 = ldg64_el(d_AB16 + (size_t)s0 * 256 + lane * 4, pol);
        uint2 rc0 = ldg64_el(d_AB16 + (size_t)t0 * 256 + 128 + lane * 4, pol);
        uint2 ra1 = ldg64_el(d_AB16 + (size_t)s1 * 256 + lane * 4, pol);
        uint2 rc1 = ldg64_el(d_AB16 + (size_t)t1 * 256 + 128 + lane * 4, pol);

        float4 a0 = h4_to_f4(ra0), c0 = h4_to_f4(rc0);
        float4 a1 = h4_to_f4(ra1), c1 = h4_to_f4(rc1);

        float acc0 = fmaxf(a0.x + c0.x, 0.f) * w2.x + fmaxf(a0.y + c0.y, 0.f) * w2.y
                   + fmaxf(a0.z + c0.z, 0.f) * w2.z + fmaxf(a0.w + c0.w, 0.f) * w2.w;
        float acc1 = fmaxf(a1.x + c1.x, 0.f) * w2.x + fmaxf(a1.y + c1.y, 0.f) * w2.y
                   + fmaxf(a1.z + c1.z, 0.f) * w2.z + fmaxf(a1.w + c1.w, 0.f) * w2.w;

        #pragma unroll
        for (int o = 16; o; o >>= 1) {
            acc0 += __shfl_xor_sync(0xffffffffu, acc0, o);
            acc1 += __shfl_xor_sync(0xffffffffu, acc1, o);
        }
        if (lane == 0) {
            float lg0 = acc0 + bb2;
            __stcs(&d_logits[e0], lg0);
            lmax = fmaxf(lmax, lg0);
            if (has1) {
                float lg1 = acc1 + bb2;
                __stcs(&d_logits[e1], lg1);
                lmax = fmaxf(lmax, lg1);
            }
        }
    }

    __shared__ float sm[8];
    #pragma unroll
    for (int o = 16; o; o >>= 1) lmax = fmaxf(lmax, __shfl_xor_sync(0xffffffffu, lmax, o));
    if (lane == 0) sm[wl] = lmax;
    __syncthreads();
    if (threadIdx.x == 0) {
        float m = sm[0];
        #pragma unroll
        for (int i = 1; i < 8; i++) m = fmaxf(m, sm[i]);
        d_partial[blockIdx.x] = m;
    }
}

// ---------------------------------------------------------------------------
// expsum: every block redundantly reduces the edge-block maxima, then
// accumulates sum of exp(logit - gmax) -> d_partial2[block]
__global__ __launch_bounds__(256)
void k_expsum(int E, int nmax) {
    __shared__ float red[8];
    __shared__ float s_gmax;
    float m = -3.402823466e38f;
    for (int i = threadIdx.x; i < nmax; i += blockDim.x) m = fmaxf(m, d_partial[i]);
    #pragma unroll
    for (int o = 16; o; o >>= 1) m = fmaxf(m, __shfl_xor_sync(0xffffffffu, m, o));
    if ((threadIdx.x & 31) == 0) red[threadIdx.x >> 5] = m;
    __syncthreads();
    if (threadIdx.x == 0) {
        float v = red[0];
        #pragma unroll
        for (int i = 1; i < 8; i++) v = fmaxf(v, red[i]);
        s_gmax = v;
    }
    __syncthreads();
    float gmax = s_gmax;

    float s = 0.f;
    int stride = gridDim.x * blockDim.x;
    for (int i = blockIdx.x * blockDim.x + threadIdx.x; i < E; i += stride)
        s += expf(__ldcs(&d_logits[i]) - gmax);
    __syncthreads();
    #pragma unroll
    for (int o = 16; o; o >>= 1) s += __shfl_xor_sync(0xffffffffu, s, o);
    if ((threadIdx.x & 31) == 0) red[threadIdx.x >> 5] = s;
    __syncthreads();
    if (threadIdx.x == 0) {
        float t = 0.f;
        #pragma unroll
        for (int i = 0; i < 8; i++) t += red[i];
        d_partial2[blockIdx.x] = t;
    }
}

// write pass: redundant scalar reductions per block, then
// out = exp(logit - gmax) * inv_sum
__global__ __launch_bounds__(256)
void k_write(float* __restrict__ out, int E, int nmax, int nsum) {
    __shared__ float red[8];
    __shared__ float s_gmax, s_inv;
    float m = -3.402823466e38f;
    for (int i = threadIdx.x; i < nmax; i += blockDim.x) m = fmaxf(m, d_partial[i]);
    #pragma unroll
    for (int o = 16; o; o >>= 1) m = fmaxf(m, __shfl_xor_sync(0xffffffffu, m, o));
    if ((threadIdx.x & 31) == 0) red[threadIdx.x >> 5] = m;
    __syncthreads();
    if (threadIdx.x == 0) {
        float v = red[0];
        #pragma unroll
        for (int i = 1; i < 8; i++) v = fmaxf(v, red[i]);
        s_gmax = v;
    }
    __syncthreads();
    float gmax = s_gmax;
    __syncthreads();

    float s = 0.f;
    for (int i = threadIdx.x; i < nsum; i += blockDim.x) s += d_partial2[i];
    #pragma unroll
    for (int o = 16; o; o >>= 1) s += __shfl_xor_sync(0xffffffffu, s, o);
    if ((threadIdx.x & 31) == 0) red[threadIdx.x >> 5] = s;
    __syncthreads();
    if (threadIdx.x == 0) {
        float t = 0.f;
        #pragma unroll
        for (int i = 0; i < 8; i++) t += red[i];
        s_inv = 1.f / t;
    }
    __syncthreads();
    float inv = s_inv;

    int stride = gridDim.x * blockDim.x;
    for (int i = blockIdx.x * blockDim.x + threadIdx.x; i < E; i += stride)
        __stcs(&out[i], expf(__ldcs(&d_logits[i]) - gmax) * inv);
}

// ---------------------------------------------------------------------------
extern "C" void kernel_launch(void* const* d_in, const int* in_sizes, int n_in,
                              void* d_out, int out_size) {
    const float*    emb  = (const float*)d_in[0];
    const unsigned* lm32 = (const unsigned*)d_in[1];
    const float*    W1   = (const float*)d_in[2];
    const float*    b1   = (const float*)d_in[3];
    const float*    W2   = (const float*)d_in[4];
    const float*    b2   = (const float*)d_in[5];
    float* out = (float*)d_out;

    int nNodes = in_sizes[0] / HID;
    int E = in_sizes[1] / 2;
    if (nNodes > NMAX) nNodes = NMAX;
    if (E > EMAX) E = EMAX;

    const int SMEM = (128 * 256 + TROWS * 128) * (int)sizeof(float);  // 163840
    cudaFuncSetAttribute(k_precompute, cudaFuncAttributeMaxDynamicSharedMemorySize, SMEM);

    k_init<<<1, 1>>>();
    k_detect<<<256, 256>>>(lm32, 2 * E);
    k_precompute<<<148, PT, SMEM>>>(emb, W1, b1, nNodes);
    k_edges<<<1184, 256>>>(lm32, W2, b2, E);     // 8 blocks/SM -> occ ~97%
    k_expsum<<<1024, 256>>>(E, 1184);
    k_write<<<1024, 256>>>(out, E, 1184, 1024);
}

// round 11
// speedup vs baseline: 2.1184x; 1.4204x over previous
#include <cuda_runtime.h>
#include <cuda_fp16.h>
#include <cstdint>

// ============================================================================
// RelationalPolicyHead: probs = softmax( relu([emb[s],emb[t]] @ W1 + b1) @ W2 + b2 )
//
// Factorization: A[n] = emb[n] @ W1[:128] + b1 ; B[n] = emb[n] @ W1[128:]
//   logit[e] = sum_j relu(A[s_e][j] + B[t_e][j]) * W2[j] + b2
// Precompute GEMM runs on tensor cores via mma.sync.m16n8k16 (fp16 in, fp32
// accum) — the non-'a' tensor path (harness targets compute_103 base, so
// tcgen05 is unavailable). AB table stored FP16 (51 MB, L2-resident).
// ============================================================================

#define HID 128
#define NMAX 100000
#define EMAX 1000000

__device__ __half d_AB16[(size_t)NMAX * 256];   // per node: [A(128) | B(128)] fp16
__device__ __half d_W1h[256 * 128];             // W1 as [n][k] row-major fp16
__device__ float d_logits[EMAX];
__device__ float d_partial[2048];
__device__ float d_partial2[2048];
__device__ unsigned d_flag;

typedef unsigned long long u64;
typedef unsigned int u32;

// ---- PTX helpers -----------------------------------------------------------
__device__ __forceinline__ u64 mkpolicy_el() {
    u64 p;
    asm("createpolicy.fractional.L2::evict_last.b64 %0, 1.0;" : "=l"(p));
    return p;
}
__device__ __forceinline__ uint2 ldg64_el(const __half* p, u64 pol) {
    uint2 v;
    asm("ld.global.nc.L2::cache_hint.v2.b32 {%0,%1}, [%2], %3;"
        : "=r"(v.x), "=r"(v.y) : "l"(p), "l"(pol));
    return v;
}
__device__ __forceinline__ float4 h4_to_f4(uint2 r) {
    __half2 h01 = *reinterpret_cast<__half2*>(&r.x);
    __half2 h23 = *reinterpret_cast<__half2*>(&r.y);
    float2 f01 = __half22float2(h01);
    float2 f23 = __half22float2(h23);
    return make_float4(f01.x, f01.y, f23.x, f23.y);
}
__device__ __forceinline__ u32 smem_u32(const void* p) {
    u32 a;
    asm("{ .reg .u64 t; cvta.to.shared.u64 t, %1; cvt.u32.u64 %0, t; }"
        : "=r"(a) : "l"(p));
    return a;
}
__device__ __forceinline__ void ldmx4(u32& r0, u32& r1, u32& r2, u32& r3, u32 addr) {
    asm volatile("ldmatrix.sync.aligned.m8n8.x4.shared.b16 {%0,%1,%2,%3}, [%4];"
                 : "=r"(r0), "=r"(r1), "=r"(r2), "=r"(r3) : "r"(addr));
}
__device__ __forceinline__ void mma16816(float* d, const u32* a, const u32* b) {
    asm volatile(
        "mma.sync.aligned.m16n8k16.row.col.f32.f16.f16.f32 "
        "{%0,%1,%2,%3}, {%4,%5,%6,%7}, {%8,%9}, {%0,%1,%2,%3};"
        : "+f"(d[0]), "+f"(d[1]), "+f"(d[2]), "+f"(d[3])
        : "r"(a[0]), "r"(a[1]), "r"(a[2]), "r"(a[3]), "r"(b[0]), "r"(b[1]));
}

// ---------------------------------------------------------------------------
__global__ void k_init() { d_flag = 0u; }

// detect index dtype: probe ONLY first 2E words (exist in both layouts).
__global__ void k_detect(const unsigned* __restrict__ lm32, int nwords) {
    unsigned acc = 0;
    int stride = gridDim.x * blockDim.x;
    int npairs = nwords >> 1;
    for (int i = blockIdx.x * blockDim.x + threadIdx.x; i < npairs; i += stride)
        acc |= __ldcs(&lm32[2 * i + 1]);
    #pragma unroll
    for (int o = 16; o; o >>= 1) acc |= __shfl_xor_sync(0xffffffffu, acc, o);
    if ((threadIdx.x & 31) == 0 && acc) atomicOr(&d_flag, acc);
}

// ---------------------------------------------------------------------------
// prep: W1 [256 x 128] fp32 -> fp16 [n][k] row-major.
// n<128: A half -> W1[k*128 + n]; n>=128: B half -> W1[(128+k)*128 + (n-128)]
__global__ void k_prepW(const float* __restrict__ W1) {
    int stride = gridDim.x * blockDim.x;
    for (int idx = blockIdx.x * blockDim.x + threadIdx.x; idx < 256 * 128; idx += stride) {
        int kglob = idx >> 7;        // W1 row in [0,256)
        int j = idx & 127;           // W1 col
        int n = (kglob < 128) ? j : (j + 128);
        int k = kglob & 127;
        d_W1h[n * 128 + k] = __float2half(__ldg(&W1[idx]));
    }
}

// ---------------------------------------------------------------------------
// GEMM: CTA tile 128 rows x 256 cols x K=128, fp16 mma.sync, fp32 accum.
// smem: A tile 128x128 fp16 (32KB, 16B-chunk XOR swizzle), B tile 256x128
// fp16 (64KB, same swizzle), b1 (512B). Warp tile 64x64 (8 warps: 2x4).
#define SM_A 0
#define SM_B 32768
#define SM_B1 98304
#define GSMEM 98816

__global__ __launch_bounds__(256, 1)
void k_gemm(const float* __restrict__ emb,
            const float* __restrict__ b1,
            int nNodes) {
    extern __shared__ char smem[];
    const u32 sbase = smem_u32(smem);
    const int tid = threadIdx.x;
    const int wid = tid >> 5;
    const int lane = tid & 31;
    const int row0 = blockIdx.x * 128;

    // stage b1
    if (tid < 128) *((float*)(smem + SM_B1) + tid) = __ldg(&b1[tid]);

    // stage A: emb rows row0..row0+127, fp32->fp16, swizzled 16B chunks.
    // chunk q: r = q/16 (row), c = q%16 (k-chunk of 8 halves)
    // dst uint4 index = r*16 + (c ^ (r&7))
    {
        uint4* aS = (uint4*)(smem + SM_A);
        for (int q = tid; q < 128 * 16; q += 256) {
            int r = q >> 4, c = q & 15;
            int row = row0 + r;
            uint4 o;
            if (row < nNodes) {
                const float4* src = (const float4*)emb + (size_t)row * 32 + c * 2;
                float4 e0 = __ldcs(src);
                float4 e1 = __ldcs(src + 1);
                __half2 h0 = __floats2half2_rn(e0.x, e0.y);
                __half2 h1 = __floats2half2_rn(e0.z, e0.w);
                __half2 h2 = __floats2half2_rn(e1.x, e1.y);
                __half2 h3 = __floats2half2_rn(e1.z, e1.w);
                o.x = *reinterpret_cast<u32*>(&h0);
                o.y = *reinterpret_cast<u32*>(&h1);
                o.z = *reinterpret_cast<u32*>(&h2);
                o.w = *reinterpret_cast<u32*>(&h3);
            } else {
                o = make_uint4(0, 0, 0, 0);
            }
            aS[r * 16 + (c ^ (r & 7))] = o;
        }
    }
    // stage B: d_W1h rows 0..255 (already fp16 [n][k]), swizzled copy
    {
        uint4* bS = (uint4*)(smem + SM_B);
        const uint4* src = (const uint4*)d_W1h;
        for (int q = tid; q < 256 * 16; q += 256) {
            int r = q >> 4, c = q & 15;
            bS[r * 16 + (c ^ (r & 7))] = __ldg(&src[q]);
        }
    }
    __syncthreads();

    // warp tiling: rw = wid&1 (row group of 64), cw = wid>>1 (col group of 64)
    const int rwbase = (wid & 1) * 64;
    const int cwbase = (wid >> 1) * 64;
    const int j = lane >> 3;       // ldmatrix sub-matrix id
    const int i = lane & 7;        // row within sub-matrix

    // per-lane A addressing: matrices (m0-7,k0),(m8-15,k0),(m0-7,k8),(m8-15,k8)
    const int rowA = rwbase + ((j & 1) << 3) + i;
    const int swA = rowA & 7;
    const int kjA = j >> 1;
    // per-lane B addressing: matrices (n0-7,k0),(n0-7,k8),(n8-15,k0),(n8-15,k8)
    const int rowB = cwbase + ((j >> 1) << 3) + i;
    const int swB = rowB & 7;
    const int kjB = j & 1;

    float d[4][8][4];
    #pragma unroll
    for (int mt = 0; mt < 4; mt++)
        #pragma unroll
        for (int nt = 0; nt < 8; nt++)
            #pragma unroll
            for (int c = 0; c < 4; c++) d[mt][nt][c] = 0.f;

    #pragma unroll
    for (int ks = 0; ks < 8; ks++) {
        u32 af[4][4];
        #pragma unroll
        for (int mt = 0; mt < 4; mt++) {
            int row = rowA + mt * 16;
            u32 addr = sbase + SM_A + (u32)((row * 16 + ((2 * ks + kjA) ^ swA)) * 16);
            ldmx4(af[mt][0], af[mt][1], af[mt][2], af[mt][3], addr);
        }
        u32 bf[8][2];
        #pragma unroll
        for (int np = 0; np < 4; np++) {
            int row = rowB + np * 16;
            u32 addr = sbase + SM_B + (u32)((row * 16 + ((2 * ks + kjB) ^ swB)) * 16);
            u32 r0, r1, r2, r3;
            ldmx4(r0, r1, r2, r3, addr);
            bf[np * 2][0] = r0;     bf[np * 2][1] = r1;
            bf[np * 2 + 1][0] = r2; bf[np * 2 + 1][1] = r3;
        }
        #pragma unroll
        for (int mt = 0; mt < 4; mt++)
            #pragma unroll
            for (int nt = 0; nt < 8; nt++)
                mma16816(d[mt][nt], af[mt], bf[nt]);
    }

    // epilogue: thread holds (m = mt*16 + lane/4 (+8), n = nt*8 + 2*(lane%4) (+1))
    {
        const float* b1s = (const float*)(smem + SM_B1);
        const int qr = lane >> 2;
        const int tq = lane & 3;
        #pragma unroll
        for (int mt = 0; mt < 4; mt++) {
            #pragma unroll
            for (int half = 0; half < 2; half++) {
                int m = rwbase + mt * 16 + qr + half * 8;
                int grow = row0 + m;
                if (grow < nNodes) {
                    __half* dst = d_AB16 + (size_t)grow * 256;
                    #pragma unroll
                    for (int nt = 0; nt < 8; nt++) {
                        int n = cwbase + nt * 8 + (tq << 1);
                        float v0 = d[mt][nt][half * 2];
                        float v1 = d[mt][nt][half * 2 + 1];
                        if (n < 128) { v0 += b1s[n]; v1 += b1s[n + 1]; }
                        __half2 h = __floats2half2_rn(v0, v1);
                        *reinterpret_cast<__half2*>(dst + n) = h;
                    }
                }
            }
        }
    }
}

// ---------------------------------------------------------------------------
// edge kernel: warp per edge (2 in flight), fp16 gathers w/ evict_last.
__global__ __launch_bounds__(256, 8)
void k_edges(const unsigned* __restrict__ lm32,
             const float* __restrict__ W2, const float* __restrict__ b2, int E) {
    const int lane = threadIdx.x & 31;
    const int wl   = threadIdx.x >> 5;
    const int gw = (blockIdx.x * blockDim.x + threadIdx.x) >> 5;
    const int nw = (gridDim.x * blockDim.x) >> 5;
    const bool is64 = (d_flag == 0u);
    const u64 pol = mkpolicy_el();

    float4 w2 = __ldg((const float4*)W2 + lane);
    float bb2 = __ldg(b2);
    float lmax = -3.402823466e38f;

    for (int e0 = gw; e0 < E; e0 += 2 * nw) {
        int e1 = e0 + nw;
        bool has1 = (e1 < E);
        int ee1 = has1 ? e1 : e0;
        int s0, t0, s1, t1;
        if (is64) {
            s0 = (int)__ldcs(&lm32[2 * e0]);  t0 = (int)__ldcs(&lm32[2 * (E + e0)]);
            s1 = (int)__ldcs(&lm32[2 * ee1]); t1 = (int)__ldcs(&lm32[2 * (E + ee1)]);
        } else {
            s0 = (int)__ldcs(&lm32[e0]);      t0 = (int)__ldcs(&lm32[E + e0]);
            s1 = (int)__ldcs(&lm32[ee1]);     t1 = (int)__ldcs(&lm32[E + ee1]);
        }

        uint2 ra0 = ldg64_el(d_AB16 + (size_t)s0 * 256 + lane * 4, pol);
        uint2 rc0 = ldg64_el(d_AB16 + (size_t)t0 * 256 + 128 + lane * 4, pol);
        uint2 ra1 = ldg64_el(d_AB16 + (size_t)s1 * 256 + lane * 4, pol);
        uint2 rc1 = ldg64_el(d_AB16 + (size_t)t1 * 256 + 128 + lane * 4, pol);

        float4 a0 = h4_to_f4(ra0), c0 = h4_to_f4(rc0);
        float4 a1 = h4_to_f4(ra1), c1 = h4_to_f4(rc1);

        float acc0 = fmaxf(a0.x + c0.x, 0.f) * w2.x + fmaxf(a0.y + c0.y, 0.f) * w2.y
                   + fmaxf(a0.z + c0.z, 0.f) * w2.z + fmaxf(a0.w + c0.w, 0.f) * w2.w;
        float acc1 = fmaxf(a1.x + c1.x, 0.f) * w2.x + fmaxf(a1.y + c1.y, 0.f) * w2.y
                   + fmaxf(a1.z + c1.z, 0.f) * w2.z + fmaxf(a1.w + c1.w, 0.f) * w2.w;

        #pragma unroll
        for (int o = 16; o; o >>= 1) {
            acc0 += __shfl_xor_sync(0xffffffffu, acc0, o);
            acc1 += __shfl_xor_sync(0xffffffffu, acc1, o);
        }
        if (lane == 0) {
            float lg0 = acc0 + bb2;
            __stcs(&d_logits[e0], lg0);
            lmax = fmaxf(lmax, lg0);
            if (has1) {
                float lg1 = acc1 + bb2;
                __stcs(&d_logits[e1], lg1);
                lmax = fmaxf(lmax, lg1);
            }
        }
    }

    __shared__ float sm[8];
    #pragma unroll
    for (int o = 16; o; o >>= 1) lmax = fmaxf(lmax, __shfl_xor_sync(0xffffffffu, lmax, o));
    if (lane == 0) sm[wl] = lmax;
    __syncthreads();
    if (threadIdx.x == 0) {
        float m = sm[0];
        #pragma unroll
        for (int i = 1; i < 8; i++) m = fmaxf(m, sm[i]);
        d_partial[blockIdx.x] = m;
    }
}

// ---------------------------------------------------------------------------
__global__ __launch_bounds__(256)
void k_expsum(int E, int nmax) {
    __shared__ float red[8];
    __shared__ float s_gmax;
    float m = -3.402823466e38f;
    for (int i = threadIdx.x; i < nmax; i += blockDim.x) m = fmaxf(m, d_partial[i]);
    #pragma unroll
    for (int o = 16; o; o >>= 1) m = fmaxf(m, __shfl_xor_sync(0xffffffffu, m, o));
    if ((threadIdx.x & 31) == 0) red[threadIdx.x >> 5] = m;
    __syncthreads();
    if (threadIdx.x == 0) {
        float v = red[0];
        #pragma unroll
        for (int i = 1; i < 8; i++) v = fmaxf(v, red[i]);
        s_gmax = v;
    }
    __syncthreads();
    float gmax = s_gmax;

    float s = 0.f;
    int stride = gridDim.x * blockDim.x;
    for (int i = blockIdx.x * blockDim.x + threadIdx.x; i < E; i += stride)
        s += expf(__ldcs(&d_logits[i]) - gmax);
    __syncthreads();
    #pragma unroll
    for (int o = 16; o; o >>= 1) s += __shfl_xor_sync(0xffffffffu, s, o);
    if ((threadIdx.x & 31) == 0) red[threadIdx.x >> 5] = s;
    __syncthreads();
    if (threadIdx.x == 0) {
        float t = 0.f;
        #pragma unroll
        for (int i = 0; i < 8; i++) t += red[i];
        d_partial2[blockIdx.x] = t;
    }
}

__global__ __launch_bounds__(256)
void k_write(float* __restrict__ out, int E, int nmax, int nsum) {
    __shared__ float red[8];
    __shared__ float s_gmax, s_inv;
    float m = -3.402823466e38f;
    for (int i = threadIdx.x; i < nmax; i += blockDim.x) m = fmaxf(m, d_partial[i]);
    #pragma unroll
    for (int o = 16; o; o >>= 1) m = fmaxf(m, __shfl_xor_sync(0xffffffffu, m, o));
    if ((threadIdx.x & 31) == 0) red[threadIdx.x >> 5] = m;
    __syncthreads();
    if (threadIdx.x == 0) {
        float v = red[0];
        #pragma unroll
        for (int i = 1; i < 8; i++) v = fmaxf(v, red[i]);
        s_gmax = v;
    }
    __syncthreads();
    float gmax = s_gmax;
    __syncthreads();

    float s = 0.f;
    for (int i = threadIdx.x; i < nsum; i += blockDim.x) s += d_partial2[i];
    #pragma unroll
    for (int o = 16; o; o >>= 1) s += __shfl_xor_sync(0xffffffffu, s, o);
    if ((threadIdx.x & 31) == 0) red[threadIdx.x >> 5] = s;
    __syncthreads();
    if (threadIdx.x == 0) {
        float t = 0.f;
        #pragma unroll
        for (int i = 0; i < 8; i++) t += red[i];
        s_inv = 1.f / t;
    }
    __syncthreads();
    float inv = s_inv;

    int stride = gridDim.x * blockDim.x;
    for (int i = blockIdx.x * blockDim.x + threadIdx.x; i < E; i += stride)
        __stcs(&out[i], expf(__ldcs(&d_logits[i]) - gmax) * inv);
}

// ---------------------------------------------------------------------------
extern "C" void kernel_launch(void* const* d_in, const int* in_sizes, int n_in,
                              void* d_out, int out_size) {
    const float*    emb  = (const float*)d_in[0];
    const unsigned* lm32 = (const unsigned*)d_in[1];
    const float*    W1   = (const float*)d_in[2];
    const float*    b1   = (const float*)d_in[3];
    const float*    W2   = (const float*)d_in[4];
    const float*    b2   = (const float*)d_in[5];
    float* out = (float*)d_out;

    int nNodes = in_sizes[0] / HID;
    int E = in_sizes[1] / 2;
    if (nNodes > NMAX) nNodes = NMAX;
    if (E > EMAX) E = EMAX;

    cudaFuncSetAttribute(k_gemm, cudaFuncAttributeMaxDynamicSharedMemorySize, GSMEM);

    int nTiles = (nNodes + 127) / 128;

    k_init<<<1, 1>>>();
    k_detect<<<256, 256>>>(lm32, 2 * E);
    k_prepW<<<64, 256>>>(W1);
    k_gemm<<<nTiles, 256, GSMEM>>>(emb, b1, nNodes);
    k_edges<<<1184, 256>>>(lm32, W2, b2, E);
    k_expsum<<<1024, 256>>>(E, 1184);
    k_write<<<1024, 256>>>(out, E, 1184, 1024);
}